// round 13
// baseline (speedup 1.0000x reference)
#include <cuda_runtime.h>
#include <cuda_fp16.h>
#include <math.h>
#include <stdint.h>

#define N_NODES 50000
#define E_EDGES 800000
#define E_TOT   850000   // edges + self loops
#define HID 64
#define CLS 40

// ---------------- scratch (__device__ globals: allocation-free) ----------------
__device__ __half2 g_h16[N_NODES * 32];   // GEMM output (fp16), gathered by edge kernel
__device__ float   g_hf[N_NODES * HID];   // edge output (fp32), GEMM input next layer
__device__ float   g_ssrc[N_NODES];
__device__ float   g_sdst[N_NODES];
__device__ int     g_cnt[N_NODES];        // zero-init; re-zeroed by k_offsets each call
__device__ int     g_off[N_NODES];
__device__ int     g_end[N_NODES];
__device__ int     g_cur[N_NODES];
__device__ int     g_csrc[E_TOT];
__device__ int     g_cursor;              // re-zeroed by k_hist each call

// ---------------- CSR build ----------------
// 8 edges per thread (2x int4) for MLP; kernels are latency-bound, not BW-bound.
__global__ void k_hist(const int* __restrict__ ei) {
    int i8 = blockIdx.x * blockDim.x + threadIdx.x;
    if (i8 == 0) g_cursor = 0;
    if (i8 < E_EDGES / 8) {
        int4 d0 = reinterpret_cast<const int4*>(ei + E_EDGES)[2 * i8];
        int4 d1 = reinterpret_cast<const int4*>(ei + E_EDGES)[2 * i8 + 1];
        if ((unsigned)d0.x < N_NODES) atomicAdd(&g_cnt[d0.x], 1);
        if ((unsigned)d0.y < N_NODES) atomicAdd(&g_cnt[d0.y], 1);
        if ((unsigned)d0.z < N_NODES) atomicAdd(&g_cnt[d0.z], 1);
        if ((unsigned)d0.w < N_NODES) atomicAdd(&g_cnt[d0.w], 1);
        if ((unsigned)d1.x < N_NODES) atomicAdd(&g_cnt[d1.x], 1);
        if ((unsigned)d1.y < N_NODES) atomicAdd(&g_cnt[d1.y], 1);
        if ((unsigned)d1.z < N_NODES) atomicAdd(&g_cnt[d1.z], 1);
        if ((unsigned)d1.w < N_NODES) atomicAdd(&g_cnt[d1.w], 1);
    }
}

// warp-aggregated atomic segment allocation (CSR valid regardless of segment order)
__global__ void k_offsets() {
    int idx  = blockIdx.x * blockDim.x + threadIdx.x;
    int lane = threadIdx.x & 31;
    int v = 0;
    if (idx < N_NODES) { v = g_cnt[idx] + 1; g_cnt[idx] = 0; }  // +1 self loop; re-zero
    int incl = v;
    #pragma unroll
    for (int s = 1; s < 32; s <<= 1) {
        int t = __shfl_up_sync(0xffffffffu, incl, s);
        if (lane >= s) incl += t;
    }
    int tot = __shfl_sync(0xffffffffu, incl, 31);
    int base = 0;
    if (lane == 0) base = atomicAdd(&g_cursor, tot);
    base = __shfl_sync(0xffffffffu, base, 0);
    if (idx < N_NODES) {
        int excl = base + incl - v;
        g_off[idx] = excl;
        g_cur[idx] = excl;
        g_end[idx] = excl + v;
    }
}

__global__ void k_fill(const int* __restrict__ ei) {
    int i8 = blockIdx.x * blockDim.x + threadIdx.x;
    const int Q = E_EDGES / 8;
    if (i8 < Q) {
        int4 s0 = reinterpret_cast<const int4*>(ei)[2 * i8];
        int4 s1 = reinterpret_cast<const int4*>(ei)[2 * i8 + 1];
        int4 d0 = reinterpret_cast<const int4*>(ei + E_EDGES)[2 * i8];
        int4 d1 = reinterpret_cast<const int4*>(ei + E_EDGES)[2 * i8 + 1];
        if ((unsigned)d0.x < N_NODES && (unsigned)s0.x < N_NODES) g_csrc[atomicAdd(&g_cur[d0.x], 1)] = s0.x;
        if ((unsigned)d0.y < N_NODES && (unsigned)s0.y < N_NODES) g_csrc[atomicAdd(&g_cur[d0.y], 1)] = s0.y;
        if ((unsigned)d0.z < N_NODES && (unsigned)s0.z < N_NODES) g_csrc[atomicAdd(&g_cur[d0.z], 1)] = s0.z;
        if ((unsigned)d0.w < N_NODES && (unsigned)s0.w < N_NODES) g_csrc[atomicAdd(&g_cur[d0.w], 1)] = s0.w;
        if ((unsigned)d1.x < N_NODES && (unsigned)s1.x < N_NODES) g_csrc[atomicAdd(&g_cur[d1.x], 1)] = s1.x;
        if ((unsigned)d1.y < N_NODES && (unsigned)s1.y < N_NODES) g_csrc[atomicAdd(&g_cur[d1.y], 1)] = s1.y;
        if ((unsigned)d1.z < N_NODES && (unsigned)s1.z < N_NODES) g_csrc[atomicAdd(&g_cur[d1.z], 1)] = s1.z;
        if ((unsigned)d1.w < N_NODES && (unsigned)s1.w < N_NODES) g_csrc[atomicAdd(&g_cur[d1.w], 1)] = s1.w;
    } else {
        int id = i8 - Q;
        if (id < N_NODES) g_csrc[atomicAdd(&g_cur[id], 1)] = id;  // self loop
    }
}

// ---------------- fused GEMM: H = X@W (stored fp16), s_src/s_dst fused (fp32) -----
// 128 rows x 64 cols per block, 256 threads, 8x4 microtile; A tile K-staged (KS=32)
// with register-prefetch software pipeline (next stage's GMEM loads overlap compute).
template <int F, int KS>
__global__ void __launch_bounds__(256, 3)
k_gemm(const float* __restrict__ X, const float* __restrict__ W,
       int Ocols,
       const float* __restrict__ asrc, const float* __restrict__ adst,
       __half2* __restrict__ H) {
    extern __shared__ float sm[];
    float* As = sm;               // [KS][132]  (k-major, padded; 132*4 % 16 == 0)
    float* Bs = As + KS * 132;    // [F][64]    (full W tile)
    float* sa = Bs + F * 64;      // [64]
    float* sb = sa + 64;          // [64]
    const int tid = threadIdx.x;
    const int node0 = blockIdx.x * 128;
    const int KQ = F / 4;

    if (tid < 64) {
        sa[tid] = (tid < Ocols) ? asrc[tid] : 0.f;
        sb[tid] = (tid < Ocols) ? adst[tid] : 0.f;
    }
    for (int idx = tid; idx < F * 64; idx += 256) {
        int k = idx >> 6, n = idx & 63;
        Bs[idx] = (n < Ocols) ? W[k * Ocols + n] : 0.f;
    }

    // prefetch stage 0 into registers (each thread owns 4 float4 of the stage)
    float4 pre[4];
    #pragma unroll
    for (int j = 0; j < 4; j++) {
        int li = tid + j * 256;
        int m = li >> 3, kq = li & 7;
        int row = node0 + m;
        if (row >= N_NODES) row = N_NODES - 1;   // clamp; stores guarded below
        pre[j] = reinterpret_cast<const float4*>(X)[row * KQ + kq];
    }

    const int n0 = (tid & 15) * 4;
    const int m0 = (tid >> 4) * 8;
    float acc[8][4];
    #pragma unroll
    for (int i = 0; i < 8; i++)
        #pragma unroll
        for (int j = 0; j < 4; j++) acc[i][j] = 0.f;

    for (int ks = 0; ks < F; ks += KS) {
        __syncthreads();   // As reuse guard (also orders Bs/sa/sb on first pass)
        #pragma unroll
        for (int j = 0; j < 4; j++) {
            int li = tid + j * 256;
            int m = li >> 3, kq = li & 7;
            int k = kq * 4;
            As[(k + 0) * 132 + m] = pre[j].x;
            As[(k + 1) * 132 + m] = pre[j].y;
            As[(k + 2) * 132 + m] = pre[j].z;
            As[(k + 3) * 132 + m] = pre[j].w;
        }
        __syncthreads();

        // issue next stage's GMEM loads now; they overlap the compute below
        if (ks + KS < F) {
            #pragma unroll
            for (int j = 0; j < 4; j++) {
                int li = tid + j * 256;
                int m = li >> 3, kq = li & 7;
                int row = node0 + m;
                if (row >= N_NODES) row = N_NODES - 1;
                pre[j] = reinterpret_cast<const float4*>(X)[row * KQ + ((ks + KS) >> 2) + kq];
            }
        }

        #pragma unroll 4
        for (int kk = 0; kk < KS; kk++) {
            float4 b  = *reinterpret_cast<const float4*>(&Bs[(ks + kk) * 64 + n0]);
            float4 al = *reinterpret_cast<const float4*>(&As[kk * 132 + m0]);
            float4 ah = *reinterpret_cast<const float4*>(&As[kk * 132 + m0 + 4]);
            acc[0][0] += al.x * b.x; acc[0][1] += al.x * b.y; acc[0][2] += al.x * b.z; acc[0][3] += al.x * b.w;
            acc[1][0] += al.y * b.x; acc[1][1] += al.y * b.y; acc[1][2] += al.y * b.z; acc[1][3] += al.y * b.w;
            acc[2][0] += al.z * b.x; acc[2][1] += al.z * b.y; acc[2][2] += al.z * b.z; acc[2][3] += al.z * b.w;
            acc[3][0] += al.w * b.x; acc[3][1] += al.w * b.y; acc[3][2] += al.w * b.z; acc[3][3] += al.w * b.w;
            acc[4][0] += ah.x * b.x; acc[4][1] += ah.x * b.y; acc[4][2] += ah.x * b.z; acc[4][3] += ah.x * b.w;
            acc[5][0] += ah.y * b.x; acc[5][1] += ah.y * b.y; acc[5][2] += ah.y * b.z; acc[5][3] += ah.y * b.w;
            acc[6][0] += ah.z * b.x; acc[6][1] += ah.z * b.y; acc[6][2] += ah.z * b.z; acc[6][3] += ah.z * b.w;
            acc[7][0] += ah.w * b.x; acc[7][1] += ah.w * b.y; acc[7][2] += ah.w * b.z; acc[7][3] += ah.w * b.w;
        }
    }

    #pragma unroll
    for (int i = 0; i < 8; i++) {
        int row = node0 + m0 + i;
        float ps = acc[i][0] * sa[n0]     + acc[i][1] * sa[n0 + 1]
                 + acc[i][2] * sa[n0 + 2] + acc[i][3] * sa[n0 + 3];
        float pd = acc[i][0] * sb[n0]     + acc[i][1] * sb[n0 + 1]
                 + acc[i][2] * sb[n0 + 2] + acc[i][3] * sb[n0 + 3];
        #pragma unroll
        for (int o = 1; o < 16; o <<= 1) {
            ps += __shfl_xor_sync(0xffffffffu, ps, o);
            pd += __shfl_xor_sync(0xffffffffu, pd, o);
        }
        if (row < N_NODES) {
            __half2 h01 = __floats2half2_rn(acc[i][0], acc[i][1]);
            __half2 h23 = __floats2half2_rn(acc[i][2], acc[i][3]);
            uint2 pk;
            pk.x = *reinterpret_cast<uint32_t*>(&h01);
            pk.y = *reinterpret_cast<uint32_t*>(&h23);
            *reinterpret_cast<uint2*>(&H[row * 32 + (n0 >> 1)]) = pk;
            if ((tid & 15) == 0) { g_ssrc[row] = ps; g_sdst[row] = pd; }
        }
    }
}

// ---------------- fused edge softmax + aggregation: one warp per dst node -------
// Quad-edge layout: lane = (eq=lane>>3, oct=lane&7). One uint4 LDG per lane covers
// 8 features of one edge; 4 edges per warp-LDG round, 2 shfl per 4 edges.
template <int OCOLS, bool GELU>
__global__ void k_edge(const __half2* __restrict__ H, const float* __restrict__ bias,
                       float* __restrict__ OUT) {
    int gw   = (blockIdx.x * blockDim.x + threadIdx.x) >> 5;
    int lane = threadIdx.x & 31;
    if (gw >= N_NODES) return;
    int s = g_off[gw], e = g_end[gw];
    float sd = g_sdst[gw];

    const int oct = lane & 7;       // feature oct: features oct*8 .. oct*8+7
    const int eq  = lane >> 3;      // edge-in-quad 0..3
    constexpr int NOCT = (OCOLS + 7) / 8;
    const bool active = (NOCT == 8) || (oct < NOCT);

    float acc[8] = {0.f, 0.f, 0.f, 0.f, 0.f, 0.f, 0.f, 0.f};
    float sum = 0.f;

    for (int i0 = s; i0 < e; i0 += 32) {
        int i = i0 + lane;
        float ex = 0.f;
        int u = 0;
        if (i < e) {
            u = g_csrc[i];
            float sc = g_ssrc[u] + sd;
            sc = sc > 0.f ? sc : 0.2f * sc;      // leaky relu, slope 0.2
            ex = __expf(sc);                      // max-shift cancels; scores bounded
            sum += ex;
        }
        int nq = (min(32, e - i0) + 3) >> 2;
        for (int q = 0; q < nq; q++) {
            int src = q * 4 + eq;
            float al = __shfl_sync(0xffffffffu, ex, src);
            int   us = __shfl_sync(0xffffffffu, u, src);
            if (active && al > 0.f) {
                uint4 pk = *reinterpret_cast<const uint4*>(H + us * 32 + oct * 4);
                float2 f0 = __half22float2(*reinterpret_cast<const __half2*>(&pk.x));
                float2 f1 = __half22float2(*reinterpret_cast<const __half2*>(&pk.y));
                float2 f2 = __half22float2(*reinterpret_cast<const __half2*>(&pk.z));
                float2 f3 = __half22float2(*reinterpret_cast<const __half2*>(&pk.w));
                acc[0] += al * f0.x; acc[1] += al * f0.y;
                acc[2] += al * f1.x; acc[3] += al * f1.y;
                acc[4] += al * f2.x; acc[5] += al * f2.y;
                acc[6] += al * f3.x; acc[7] += al * f3.y;
            }
        }
    }
    #pragma unroll
    for (int o = 16; o; o >>= 1) sum += __shfl_xor_sync(0xffffffffu, sum, o);
    // combine the 4 edge-quad groups (lanes differing in bits 3,4 share an oct)
    #pragma unroll
    for (int j = 0; j < 8; j++) {
        acc[j] += __shfl_xor_sync(0xffffffffu, acc[j], 8);
        acc[j] += __shfl_xor_sync(0xffffffffu, acc[j], 16);
    }
    float inv = 1.f / (sum + 1e-16f);

    if (eq == 0 && active) {
        float v[8];
        #pragma unroll
        for (int j = 0; j < 8; j++) {
            v[j] = acc[j] * inv + bias[oct * 8 + j];
            if (GELU) v[j] = 0.5f * v[j] * (1.f + erff(v[j] * 0.70710678118f));
        }
        float4* o = reinterpret_cast<float4*>(&OUT[gw * OCOLS + oct * 8]);
        o[0] = make_float4(v[0], v[1], v[2], v[3]);
        o[1] = make_float4(v[4], v[5], v[6], v[7]);
    }
}

// ---------------- launch ----------------
extern "C" void kernel_launch(void* const* d_in, const int* in_sizes, int n_in,
                              void* d_out, int out_size) {
    const float* x   = (const float*)d_in[0];
    const int*   ei  = (const int*)d_in[1];
    const float* W1  = (const float*)d_in[2];
    const float* as1 = (const float*)d_in[3];
    const float* ad1 = (const float*)d_in[4];
    const float* b1  = (const float*)d_in[5];
    const float* W2  = (const float*)d_in[6];
    const float* as2 = (const float*)d_in[7];
    const float* ad2 = (const float*)d_in[8];
    const float* b2  = (const float*)d_in[9];
    const float* W3  = (const float*)d_in[10];
    const float* as3 = (const float*)d_in[11];
    const float* ad3 = (const float*)d_in[12];
    const float* b3  = (const float*)d_in[13];
    float* out = (float*)d_out;

    __half2* h16;
    float*   hf;
    cudaGetSymbolAddress((void**)&h16, g_h16);
    cudaGetSymbolAddress((void**)&hf,  g_hf);

    // smem: As KS*132 + Bs F*64 + 128
    const size_t smem128 = (size_t)(32 * 132 + 128 * 64 + 128) * 4;  // 50176
    const size_t smem64  = (size_t)(32 * 132 + 64 * 64 + 128) * 4;   // 33792
    cudaFuncSetAttribute((const void*)k_gemm<128, 32>, cudaFuncAttributeMaxDynamicSharedMemorySize, (int)smem128);
    cudaFuncSetAttribute((const void*)k_gemm<64, 32>,  cudaFuncAttributeMaxDynamicSharedMemorySize, (int)smem64);

    const int gemm_grid = (N_NODES + 127) / 128;        // 391
    const int edge_grid = (N_NODES * 32 + 255) / 256;   // 6250

    // Fork a side stream (capture-legal via events) so the CSR build overlaps GEMM1.
    // Handles are leaked intentionally (destroying mid-capture is hazardous; a few
    // host objects per kernel_launch call is harmless).
    cudaStream_t s2;
    cudaStreamCreateWithFlags(&s2, cudaStreamNonBlocking);
    cudaEvent_t evFork, evJoin;
    cudaEventCreateWithFlags(&evFork, cudaEventDisableTiming);
    cudaEventCreateWithFlags(&evJoin, cudaEventDisableTiming);

    cudaEventRecord(evFork, 0);
    cudaStreamWaitEvent(s2, evFork, 0);

    // CSR build on side stream (depends only on edge_index)
    k_hist<<<(E_EDGES / 8 + 255) / 256, 256, 0, s2>>>(ei);
    k_offsets<<<(N_NODES + 1023) / 1024, 1024, 0, s2>>>();
    k_fill<<<(E_EDGES / 8 + N_NODES + 255) / 256, 256, 0, s2>>>(ei);
    cudaEventRecord(evJoin, s2);

    // GEMM1 on main stream, concurrent with CSR build
    k_gemm<128, 32><<<gemm_grid, 256, smem128>>>(x, W1, HID, as1, ad1, h16);

    // join: edge1 needs both CSR and GEMM1
    cudaStreamWaitEvent(0, evJoin, 0);
    k_edge<HID, true><<<edge_grid, 256>>>(h16, b1, hf);
    // layer 2
    k_gemm<64, 32><<<gemm_grid, 256, smem64>>>(hf, W2, HID, as2, ad2, h16);
    k_edge<HID, true><<<edge_grid, 256>>>(h16, b2, hf);
    // layer 3 (O=40, padded to 64 internally)
    k_gemm<64, 32><<<gemm_grid, 256, smem64>>>(hf, W3, CLS, as3, ad3, h16);
    k_edge<CLS, false><<<edge_grid, 256>>>(h16, b3, out);
}

// round 14
// speedup vs baseline: 1.4673x; 1.4673x over previous
#include <cuda_runtime.h>
#include <cuda_fp16.h>
#include <math.h>
#include <stdint.h>

#define N_NODES 50000
#define E_EDGES 800000
#define E_TOT   850000   // edges + self loops
#define HID 64
#define CLS 40

// ---------------- scratch (__device__ globals: allocation-free) ----------------
__device__ __half2 g_h16[N_NODES * 32];   // GEMM output (fp16), gathered by edge kernel
__device__ float   g_hf[N_NODES * HID];   // edge output (fp32), GEMM input next layer
__device__ float   g_ssrc[N_NODES];
__device__ float   g_sdst[N_NODES];
__device__ int     g_cnt[N_NODES];        // zero-init; re-zeroed by k_offsets each call
__device__ int     g_off[N_NODES];
__device__ int     g_end[N_NODES];
__device__ int     g_cur[N_NODES];
__device__ int     g_csrc[E_TOT];
__device__ int     g_cursor;              // re-zeroed by k_hist each call

// ---------------- CSR build ----------------
__global__ void k_hist(const int* __restrict__ ei) {
    int i4 = blockIdx.x * blockDim.x + threadIdx.x;
    if (i4 == 0) g_cursor = 0;
    if (i4 < E_EDGES / 4) {
        int4 d = reinterpret_cast<const int4*>(ei + E_EDGES)[i4];
        if ((unsigned)d.x < N_NODES) atomicAdd(&g_cnt[d.x], 1);
        if ((unsigned)d.y < N_NODES) atomicAdd(&g_cnt[d.y], 1);
        if ((unsigned)d.z < N_NODES) atomicAdd(&g_cnt[d.z], 1);
        if ((unsigned)d.w < N_NODES) atomicAdd(&g_cnt[d.w], 1);
    }
}

// warp-aggregated atomic segment allocation (CSR valid regardless of segment order)
__global__ void k_offsets() {
    int idx  = blockIdx.x * blockDim.x + threadIdx.x;
    int lane = threadIdx.x & 31;
    int v = 0;
    if (idx < N_NODES) { v = g_cnt[idx] + 1; g_cnt[idx] = 0; }  // +1 self loop; re-zero
    int incl = v;
    #pragma unroll
    for (int s = 1; s < 32; s <<= 1) {
        int t = __shfl_up_sync(0xffffffffu, incl, s);
        if (lane >= s) incl += t;
    }
    int tot = __shfl_sync(0xffffffffu, incl, 31);
    int base = 0;
    if (lane == 0) base = atomicAdd(&g_cursor, tot);
    base = __shfl_sync(0xffffffffu, base, 0);
    if (idx < N_NODES) {
        int excl = base + incl - v;
        g_off[idx] = excl;
        g_cur[idx] = excl;
        g_end[idx] = excl + v;
    }
}

__global__ void k_fill(const int* __restrict__ ei) {
    int i4 = blockIdx.x * blockDim.x + threadIdx.x;
    const int Q = E_EDGES / 4;
    if (i4 < Q) {
        int4 s = reinterpret_cast<const int4*>(ei)[i4];
        int4 d = reinterpret_cast<const int4*>(ei + E_EDGES)[i4];
        if ((unsigned)d.x < N_NODES && (unsigned)s.x < N_NODES) g_csrc[atomicAdd(&g_cur[d.x], 1)] = s.x;
        if ((unsigned)d.y < N_NODES && (unsigned)s.y < N_NODES) g_csrc[atomicAdd(&g_cur[d.y], 1)] = s.y;
        if ((unsigned)d.z < N_NODES && (unsigned)s.z < N_NODES) g_csrc[atomicAdd(&g_cur[d.z], 1)] = s.z;
        if ((unsigned)d.w < N_NODES && (unsigned)s.w < N_NODES) g_csrc[atomicAdd(&g_cur[d.w], 1)] = s.w;
    } else {
        int id = i4 - Q;
        if (id < N_NODES) g_csrc[atomicAdd(&g_cur[id], 1)] = id;  // self loop
    }
}

// ---------------- fused GEMM: H = X@W (stored fp16), s_src/s_dst fused (fp32) -----
// 128 rows x 64 cols per block, 256 threads, 8x4 microtile; A tile K-staged (KS).
template <int F, int KS>
__global__ void __launch_bounds__(256, 4)
k_gemm(const float* __restrict__ X, const float* __restrict__ W,
       int Ocols,
       const float* __restrict__ asrc, const float* __restrict__ adst,
       __half2* __restrict__ H) {
    extern __shared__ float sm[];
    float* As = sm;               // [KS][132]  (k-major, padded; 132*4 % 16 == 0)
    float* Bs = As + KS * 132;    // [F][64]    (full W tile)
    float* sa = Bs + F * 64;      // [64]
    float* sb = sa + 64;          // [64]
    const int tid = threadIdx.x;
    const int node0 = blockIdx.x * 128;
    const int KQ = F / 4;

    if (tid < 64) {
        sa[tid] = (tid < Ocols) ? asrc[tid] : 0.f;
        sb[tid] = (tid < Ocols) ? adst[tid] : 0.f;
    }
    for (int idx = tid; idx < F * 64; idx += 256) {
        int k = idx >> 6, n = idx & 63;
        Bs[idx] = (n < Ocols) ? W[k * Ocols + n] : 0.f;
    }

    const int n0 = (tid & 15) * 4;
    const int m0 = (tid >> 4) * 8;
    float acc[8][4];
    #pragma unroll
    for (int i = 0; i < 8; i++)
        #pragma unroll
        for (int j = 0; j < 4; j++) acc[i][j] = 0.f;

    for (int ks = 0; ks < F; ks += KS) {
        __syncthreads();   // As reuse guard (also orders Bs/sa/sb on first pass)
        constexpr int KSQ = KS / 4;
        for (int li = tid; li < 128 * KSQ; li += 256) {
            int m = li / KSQ, kq = li % KSQ;
            int row = node0 + m;
            if (row >= N_NODES) row = N_NODES - 1;   // clamp; stores guarded below
            float4 g = reinterpret_cast<const float4*>(X)[row * KQ + (ks >> 2) + kq];
            int k = kq * 4;
            As[(k + 0) * 132 + m] = g.x;
            As[(k + 1) * 132 + m] = g.y;
            As[(k + 2) * 132 + m] = g.z;
            As[(k + 3) * 132 + m] = g.w;
        }
        __syncthreads();

        #pragma unroll 4
        for (int kk = 0; kk < KS; kk++) {
            float4 b  = *reinterpret_cast<const float4*>(&Bs[(ks + kk) * 64 + n0]);
            float4 al = *reinterpret_cast<const float4*>(&As[kk * 132 + m0]);
            float4 ah = *reinterpret_cast<const float4*>(&As[kk * 132 + m0 + 4]);
            acc[0][0] += al.x * b.x; acc[0][1] += al.x * b.y; acc[0][2] += al.x * b.z; acc[0][3] += al.x * b.w;
            acc[1][0] += al.y * b.x; acc[1][1] += al.y * b.y; acc[1][2] += al.y * b.z; acc[1][3] += al.y * b.w;
            acc[2][0] += al.z * b.x; acc[2][1] += al.z * b.y; acc[2][2] += al.z * b.z; acc[2][3] += al.z * b.w;
            acc[3][0] += al.w * b.x; acc[3][1] += al.w * b.y; acc[3][2] += al.w * b.z; acc[3][3] += al.w * b.w;
            acc[4][0] += ah.x * b.x; acc[4][1] += ah.x * b.y; acc[4][2] += ah.x * b.z; acc[4][3] += ah.x * b.w;
            acc[5][0] += ah.y * b.x; acc[5][1] += ah.y * b.y; acc[5][2] += ah.y * b.z; acc[5][3] += ah.y * b.w;
            acc[6][0] += ah.z * b.x; acc[6][1] += ah.z * b.y; acc[6][2] += ah.z * b.z; acc[6][3] += ah.z * b.w;
            acc[7][0] += ah.w * b.x; acc[7][1] += ah.w * b.y; acc[7][2] += ah.w * b.z; acc[7][3] += ah.w * b.w;
        }
    }

    #pragma unroll
    for (int i = 0; i < 8; i++) {
        int row = node0 + m0 + i;
        float ps = acc[i][0] * sa[n0]     + acc[i][1] * sa[n0 + 1]
                 + acc[i][2] * sa[n0 + 2] + acc[i][3] * sa[n0 + 3];
        float pd = acc[i][0] * sb[n0]     + acc[i][1] * sb[n0 + 1]
                 + acc[i][2] * sb[n0 + 2] + acc[i][3] * sb[n0 + 3];
        #pragma unroll
        for (int o = 1; o < 16; o <<= 1) {
            ps += __shfl_xor_sync(0xffffffffu, ps, o);
            pd += __shfl_xor_sync(0xffffffffu, pd, o);
        }
        if (row < N_NODES) {
            __half2 h01 = __floats2half2_rn(acc[i][0], acc[i][1]);
            __half2 h23 = __floats2half2_rn(acc[i][2], acc[i][3]);
            uint2 pk;
            pk.x = *reinterpret_cast<uint32_t*>(&h01);
            pk.y = *reinterpret_cast<uint32_t*>(&h23);
            *reinterpret_cast<uint2*>(&H[row * 32 + (n0 >> 1)]) = pk;
            if ((tid & 15) == 0) { g_ssrc[row] = ps; g_sdst[row] = pd; }
        }
    }
}

// ---------------- fused edge softmax + aggregation: one warp per dst node -------
// Quad-edge layout: lane = (eq=lane>>3, oct=lane&7). One uint4 LDG per lane covers
// 8 features of one edge; 4 edges per warp-LDG round, 2 shfl per 4 edges.
template <int OCOLS, bool GELU>
__global__ void k_edge(const __half2* __restrict__ H, const float* __restrict__ bias,
                       float* __restrict__ OUT) {
    int gw   = (blockIdx.x * blockDim.x + threadIdx.x) >> 5;
    int lane = threadIdx.x & 31;
    if (gw >= N_NODES) return;
    int s = g_off[gw], e = g_end[gw];
    float sd = g_sdst[gw];

    const int oct = lane & 7;       // feature oct: features oct*8 .. oct*8+7
    const int eq  = lane >> 3;      // edge-in-quad 0..3
    constexpr int NOCT = (OCOLS + 7) / 8;
    const bool active = (NOCT == 8) || (oct < NOCT);

    float acc[8] = {0.f, 0.f, 0.f, 0.f, 0.f, 0.f, 0.f, 0.f};
    float sum = 0.f;

    for (int i0 = s; i0 < e; i0 += 32) {
        int i = i0 + lane;
        float ex = 0.f;
        int u = 0;
        if (i < e) {
            u = g_csrc[i];
            float sc = g_ssrc[u] + sd;
            sc = sc > 0.f ? sc : 0.2f * sc;      // leaky relu, slope 0.2
            ex = __expf(sc);                      // max-shift cancels; scores bounded
            sum += ex;
        }
        int nq = (min(32, e - i0) + 3) >> 2;
        for (int q = 0; q < nq; q++) {
            int src = q * 4 + eq;
            float al = __shfl_sync(0xffffffffu, ex, src);
            int   us = __shfl_sync(0xffffffffu, u, src);
            if (active && al > 0.f) {
                uint4 pk = *reinterpret_cast<const uint4*>(H + us * 32 + oct * 4);
                float2 f0 = __half22float2(*reinterpret_cast<const __half2*>(&pk.x));
                float2 f1 = __half22float2(*reinterpret_cast<const __half2*>(&pk.y));
                float2 f2 = __half22float2(*reinterpret_cast<const __half2*>(&pk.z));
                float2 f3 = __half22float2(*reinterpret_cast<const __half2*>(&pk.w));
                acc[0] += al * f0.x; acc[1] += al * f0.y;
                acc[2] += al * f1.x; acc[3] += al * f1.y;
                acc[4] += al * f2.x; acc[5] += al * f2.y;
                acc[6] += al * f3.x; acc[7] += al * f3.y;
            }
        }
    }
    #pragma unroll
    for (int o = 16; o; o >>= 1) sum += __shfl_xor_sync(0xffffffffu, sum, o);
    // combine the 4 edge-quad groups (lanes differing in bits 3,4 share an oct)
    #pragma unroll
    for (int j = 0; j < 8; j++) {
        acc[j] += __shfl_xor_sync(0xffffffffu, acc[j], 8);
        acc[j] += __shfl_xor_sync(0xffffffffu, acc[j], 16);
    }
    float inv = 1.f / (sum + 1e-16f);

    if (eq == 0 && active) {
        float v[8];
        #pragma unroll
        for (int j = 0; j < 8; j++) {
            v[j] = acc[j] * inv + bias[oct * 8 + j];
            if (GELU) v[j] = 0.5f * v[j] * (1.f + erff(v[j] * 0.70710678118f));
        }
        float4* o = reinterpret_cast<float4*>(&OUT[gw * OCOLS + oct * 8]);
        o[0] = make_float4(v[0], v[1], v[2], v[3]);
        o[1] = make_float4(v[4], v[5], v[6], v[7]);
    }
}

// ---------------- launch ----------------
extern "C" void kernel_launch(void* const* d_in, const int* in_sizes, int n_in,
                              void* d_out, int out_size) {
    const float* x   = (const float*)d_in[0];
    const int*   ei  = (const int*)d_in[1];
    const float* W1  = (const float*)d_in[2];
    const float* as1 = (const float*)d_in[3];
    const float* ad1 = (const float*)d_in[4];
    const float* b1  = (const float*)d_in[5];
    const float* W2  = (const float*)d_in[6];
    const float* as2 = (const float*)d_in[7];
    const float* ad2 = (const float*)d_in[8];
    const float* b2  = (const float*)d_in[9];
    const float* W3  = (const float*)d_in[10];
    const float* as3 = (const float*)d_in[11];
    const float* ad3 = (const float*)d_in[12];
    const float* b3  = (const float*)d_in[13];
    float* out = (float*)d_out;

    __half2* h16;
    float*   hf;
    cudaGetSymbolAddress((void**)&h16, g_h16);
    cudaGetSymbolAddress((void**)&hf,  g_hf);

    // smem: As KS*132 + Bs F*64 + 128
    const size_t smem128 = (size_t)(32 * 132 + 128 * 64 + 128) * 4;  // 50176
    const size_t smem64  = (size_t)(32 * 132 + 64 * 64 + 128) * 4;   // 33792
    cudaFuncSetAttribute((const void*)k_gemm<128, 32>, cudaFuncAttributeMaxDynamicSharedMemorySize, (int)smem128);
    cudaFuncSetAttribute((const void*)k_gemm<64, 32>,  cudaFuncAttributeMaxDynamicSharedMemorySize, (int)smem64);

    const int gemm_grid = (N_NODES + 127) / 128;        // 391
    const int edge_grid = (N_NODES * 32 + 255) / 256;   // 6250

    // Fork a side stream (capture-legal via events) so the CSR build overlaps GEMM1.
    // GEMM1 (the longer branch) is enqueued FIRST so its blocks get dispatch priority.
    // Handles are leaked intentionally (destroying mid-capture is hazardous; a few
    // host objects per kernel_launch call is harmless).
    cudaStream_t s2;
    cudaStreamCreateWithFlags(&s2, cudaStreamNonBlocking);
    cudaEvent_t evFork, evJoin;
    cudaEventCreateWithFlags(&evFork, cudaEventDisableTiming);
    cudaEventCreateWithFlags(&evJoin, cudaEventDisableTiming);

    cudaEventRecord(evFork, 0);
    cudaStreamWaitEvent(s2, evFork, 0);

    // GEMM1 on main stream (enqueued first -> dispatched first)
    k_gemm<128, 32><<<gemm_grid, 256, smem128>>>(x, W1, HID, as1, ad1, h16);

    // CSR build on side stream (depends only on edge_index), concurrent with GEMM1
    k_hist<<<(E_EDGES / 4 + 255) / 256, 256, 0, s2>>>(ei);
    k_offsets<<<(N_NODES + 1023) / 1024, 1024, 0, s2>>>();
    k_fill<<<(E_EDGES / 4 + N_NODES + 255) / 256, 256, 0, s2>>>(ei);
    cudaEventRecord(evJoin, s2);

    // join: edge1 needs both CSR and GEMM1
    cudaStreamWaitEvent(0, evJoin, 0);
    k_edge<HID, true><<<edge_grid, 256>>>(h16, b1, hf);
    // layer 2
    k_gemm<64, 32><<<gemm_grid, 256, smem64>>>(hf, W2, HID, as2, ad2, h16);
    k_edge<HID, true><<<edge_grid, 256>>>(h16, b2, hf);
    // layer 3 (O=40, padded to 64 internally)
    k_gemm<64, 32><<<gemm_grid, 256, smem64>>>(hf, W3, CLS, as3, ad3, h16);
    k_edge<CLS, false><<<edge_grid, 256>>>(h16, b3, out);
}

// round 15
// speedup vs baseline: 1.5155x; 1.0329x over previous
#include <cuda_runtime.h>
#include <cuda_fp16.h>
#include <math.h>
#include <stdint.h>

#define N_NODES 50000
#define E_EDGES 800000
#define E_TOT   850000   // edges + self loops
#define HID 64
#define CLS 40

// ---------------- scratch (__device__ globals: allocation-free) ----------------
__device__ __half2 g_h16[N_NODES * 32];   // GEMM output (fp16), gathered by edge kernel
__device__ float   g_hf[N_NODES * HID];   // edge output (fp32), GEMM input next layer
__device__ float   g_ssrc[N_NODES];
__device__ float   g_sdst[N_NODES];
__device__ int     g_cnt[N_NODES];        // zero-init; re-zeroed by k_offsets each call
__device__ int     g_off[N_NODES];
__device__ int     g_end[N_NODES];
__device__ int     g_cur[N_NODES];
__device__ int     g_csrc[E_TOT];
__device__ int     g_cursor;              // re-zeroed by k_hist each call

// ---------------- CSR build ----------------
__global__ void k_hist(const int* __restrict__ ei) {
    int i4 = blockIdx.x * blockDim.x + threadIdx.x;
    if (i4 == 0) g_cursor = 0;
    if (i4 < E_EDGES / 4) {
        int4 d = reinterpret_cast<const int4*>(ei + E_EDGES)[i4];
        if ((unsigned)d.x < N_NODES) atomicAdd(&g_cnt[d.x], 1);
        if ((unsigned)d.y < N_NODES) atomicAdd(&g_cnt[d.y], 1);
        if ((unsigned)d.z < N_NODES) atomicAdd(&g_cnt[d.z], 1);
        if ((unsigned)d.w < N_NODES) atomicAdd(&g_cnt[d.w], 1);
    }
}

// warp-aggregated atomic segment allocation (CSR valid regardless of segment order)
__global__ void k_offsets() {
    int idx  = blockIdx.x * blockDim.x + threadIdx.x;
    int lane = threadIdx.x & 31;
    int v = 0;
    if (idx < N_NODES) { v = g_cnt[idx] + 1; g_cnt[idx] = 0; }  // +1 self loop; re-zero
    int incl = v;
    #pragma unroll
    for (int s = 1; s < 32; s <<= 1) {
        int t = __shfl_up_sync(0xffffffffu, incl, s);
        if (lane >= s) incl += t;
    }
    int tot = __shfl_sync(0xffffffffu, incl, 31);
    int base = 0;
    if (lane == 0) base = atomicAdd(&g_cursor, tot);
    base = __shfl_sync(0xffffffffu, base, 0);
    if (idx < N_NODES) {
        int excl = base + incl - v;
        g_off[idx] = excl;
        g_cur[idx] = excl;
        g_end[idx] = excl + v;
    }
}

__global__ void k_fill(const int* __restrict__ ei) {
    int i4 = blockIdx.x * blockDim.x + threadIdx.x;
    const int Q = E_EDGES / 4;
    if (i4 < Q) {
        int4 s = reinterpret_cast<const int4*>(ei)[i4];
        int4 d = reinterpret_cast<const int4*>(ei + E_EDGES)[i4];
        if ((unsigned)d.x < N_NODES && (unsigned)s.x < N_NODES) g_csrc[atomicAdd(&g_cur[d.x], 1)] = s.x;
        if ((unsigned)d.y < N_NODES && (unsigned)s.y < N_NODES) g_csrc[atomicAdd(&g_cur[d.y], 1)] = s.y;
        if ((unsigned)d.z < N_NODES && (unsigned)s.z < N_NODES) g_csrc[atomicAdd(&g_cur[d.z], 1)] = s.z;
        if ((unsigned)d.w < N_NODES && (unsigned)s.w < N_NODES) g_csrc[atomicAdd(&g_cur[d.w], 1)] = s.w;
    } else {
        int id = i4 - Q;
        if (id < N_NODES) g_csrc[atomicAdd(&g_cur[id], 1)] = id;  // self loop
    }
}

// ---------------- fused GEMM: H = X@W (stored fp16), s_src/s_dst fused (fp32) -----
// 128 rows x 64 cols per block, 256 threads, 8x4 microtile; A tile K-staged (KS).
template <int F, int KS>
__global__ void __launch_bounds__(256, 4)
k_gemm(const float* __restrict__ X, const float* __restrict__ W,
       int Ocols,
       const float* __restrict__ asrc, const float* __restrict__ adst,
       __half2* __restrict__ H) {
    extern __shared__ float sm[];
    float* As = sm;               // [KS][132]  (k-major, padded; 132*4 % 16 == 0)
    float* Bs = As + KS * 132;    // [F][64]    (full W tile)
    float* sa = Bs + F * 64;      // [64]
    float* sb = sa + 64;          // [64]
    const int tid = threadIdx.x;
    const int node0 = blockIdx.x * 128;
    const int KQ = F / 4;

    if (tid < 64) {
        sa[tid] = (tid < Ocols) ? asrc[tid] : 0.f;
        sb[tid] = (tid < Ocols) ? adst[tid] : 0.f;
    }
    for (int idx = tid; idx < F * 64; idx += 256) {
        int k = idx >> 6, n = idx & 63;
        Bs[idx] = (n < Ocols) ? W[k * Ocols + n] : 0.f;
    }

    const int n0 = (tid & 15) * 4;
    const int m0 = (tid >> 4) * 8;
    float acc[8][4];
    #pragma unroll
    for (int i = 0; i < 8; i++)
        #pragma unroll
        for (int j = 0; j < 4; j++) acc[i][j] = 0.f;

    for (int ks = 0; ks < F; ks += KS) {
        __syncthreads();   // As reuse guard (also orders Bs/sa/sb on first pass)
        constexpr int KSQ = KS / 4;
        for (int li = tid; li < 128 * KSQ; li += 256) {
            int m = li / KSQ, kq = li % KSQ;
            int row = node0 + m;
            if (row >= N_NODES) row = N_NODES - 1;   // clamp; stores guarded below
            float4 g = reinterpret_cast<const float4*>(X)[row * KQ + (ks >> 2) + kq];
            int k = kq * 4;
            As[(k + 0) * 132 + m] = g.x;
            As[(k + 1) * 132 + m] = g.y;
            As[(k + 2) * 132 + m] = g.z;
            As[(k + 3) * 132 + m] = g.w;
        }
        __syncthreads();

        #pragma unroll 4
        for (int kk = 0; kk < KS; kk++) {
            float4 b  = *reinterpret_cast<const float4*>(&Bs[(ks + kk) * 64 + n0]);
            float4 al = *reinterpret_cast<const float4*>(&As[kk * 132 + m0]);
            float4 ah = *reinterpret_cast<const float4*>(&As[kk * 132 + m0 + 4]);
            acc[0][0] += al.x * b.x; acc[0][1] += al.x * b.y; acc[0][2] += al.x * b.z; acc[0][3] += al.x * b.w;
            acc[1][0] += al.y * b.x; acc[1][1] += al.y * b.y; acc[1][2] += al.y * b.z; acc[1][3] += al.y * b.w;
            acc[2][0] += al.z * b.x; acc[2][1] += al.z * b.y; acc[2][2] += al.z * b.z; acc[2][3] += al.z * b.w;
            acc[3][0] += al.w * b.x; acc[3][1] += al.w * b.y; acc[3][2] += al.w * b.z; acc[3][3] += al.w * b.w;
            acc[4][0] += ah.x * b.x; acc[4][1] += ah.x * b.y; acc[4][2] += ah.x * b.z; acc[4][3] += ah.x * b.w;
            acc[5][0] += ah.y * b.x; acc[5][1] += ah.y * b.y; acc[5][2] += ah.y * b.z; acc[5][3] += ah.y * b.w;
            acc[6][0] += ah.z * b.x; acc[6][1] += ah.z * b.y; acc[6][2] += ah.z * b.z; acc[6][3] += ah.z * b.w;
            acc[7][0] += ah.w * b.x; acc[7][1] += ah.w * b.y; acc[7][2] += ah.w * b.z; acc[7][3] += ah.w * b.w;
        }
    }

    #pragma unroll
    for (int i = 0; i < 8; i++) {
        int row = node0 + m0 + i;
        float ps = acc[i][0] * sa[n0]     + acc[i][1] * sa[n0 + 1]
                 + acc[i][2] * sa[n0 + 2] + acc[i][3] * sa[n0 + 3];
        float pd = acc[i][0] * sb[n0]     + acc[i][1] * sb[n0 + 1]
                 + acc[i][2] * sb[n0 + 2] + acc[i][3] * sb[n0 + 3];
        #pragma unroll
        for (int o = 1; o < 16; o <<= 1) {
            ps += __shfl_xor_sync(0xffffffffu, ps, o);
            pd += __shfl_xor_sync(0xffffffffu, pd, o);
        }
        if (row < N_NODES) {
            __half2 h01 = __floats2half2_rn(acc[i][0], acc[i][1]);
            __half2 h23 = __floats2half2_rn(acc[i][2], acc[i][3]);
            uint2 pk;
            pk.x = *reinterpret_cast<uint32_t*>(&h01);
            pk.y = *reinterpret_cast<uint32_t*>(&h23);
            *reinterpret_cast<uint2*>(&H[row * 32 + (n0 >> 1)]) = pk;
            if ((tid & 15) == 0) { g_ssrc[row] = ps; g_sdst[row] = pd; }
        }
    }
}

// ---------------- fused edge softmax + aggregation: one warp per dst node -------
// Quad-edge layout: lane = (eq=lane>>3, oct=lane&7). One uint4 LDG per lane covers
// 8 features of one edge; 4 edges per warp-LDG round, 2 shfl per 4 edges.
template <int OCOLS, bool GELU>
__global__ void k_edge(const __half2* __restrict__ H, const float* __restrict__ bias,
                       float* __restrict__ OUT) {
    int gw   = (blockIdx.x * blockDim.x + threadIdx.x) >> 5;
    int lane = threadIdx.x & 31;
    if (gw >= N_NODES) return;
    int s = g_off[gw], e = g_end[gw];
    float sd = g_sdst[gw];

    const int oct = lane & 7;       // feature oct: features oct*8 .. oct*8+7
    const int eq  = lane >> 3;      // edge-in-quad 0..3
    constexpr int NOCT = (OCOLS + 7) / 8;
    const bool active = (NOCT == 8) || (oct < NOCT);

    float acc[8] = {0.f, 0.f, 0.f, 0.f, 0.f, 0.f, 0.f, 0.f};
    float sum = 0.f;

    for (int i0 = s; i0 < e; i0 += 32) {
        int i = i0 + lane;
        float ex = 0.f;
        int u = 0;
        if (i < e) {
            u = g_csrc[i];
            float sc = g_ssrc[u] + sd;
            sc = sc > 0.f ? sc : 0.2f * sc;      // leaky relu, slope 0.2
            ex = __expf(sc);                      // max-shift cancels; scores bounded
            sum += ex;
        }
        int nq = (min(32, e - i0) + 3) >> 2;
        for (int q = 0; q < nq; q++) {
            int src = q * 4 + eq;
            float al = __shfl_sync(0xffffffffu, ex, src);
            int   us = __shfl_sync(0xffffffffu, u, src);
            if (active && al > 0.f) {
                uint4 pk = *reinterpret_cast<const uint4*>(H + us * 32 + oct * 4);
                float2 f0 = __half22float2(*reinterpret_cast<const __half2*>(&pk.x));
                float2 f1 = __half22float2(*reinterpret_cast<const __half2*>(&pk.y));
                float2 f2 = __half22float2(*reinterpret_cast<const __half2*>(&pk.z));
                float2 f3 = __half22float2(*reinterpret_cast<const __half2*>(&pk.w));
                acc[0] += al * f0.x; acc[1] += al * f0.y;
                acc[2] += al * f1.x; acc[3] += al * f1.y;
                acc[4] += al * f2.x; acc[5] += al * f2.y;
                acc[6] += al * f3.x; acc[7] += al * f3.y;
            }
        }
    }
    #pragma unroll
    for (int o = 16; o; o >>= 1) sum += __shfl_xor_sync(0xffffffffu, sum, o);
    // combine the 4 edge-quad groups (lanes differing in bits 3,4 share an oct)
    #pragma unroll
    for (int j = 0; j < 8; j++) {
        acc[j] += __shfl_xor_sync(0xffffffffu, acc[j], 8);
        acc[j] += __shfl_xor_sync(0xffffffffu, acc[j], 16);
    }
    float inv = 1.f / (sum + 1e-16f);

    if (eq == 0 && active) {
        float v[8];
        #pragma unroll
        for (int j = 0; j < 8; j++) {
            v[j] = acc[j] * inv + bias[oct * 8 + j];
            if (GELU) v[j] = 0.5f * v[j] * (1.f + erff(v[j] * 0.70710678118f));
        }
        float4* o = reinterpret_cast<float4*>(&OUT[gw * OCOLS + oct * 8]);
        o[0] = make_float4(v[0], v[1], v[2], v[3]);
        o[1] = make_float4(v[4], v[5], v[6], v[7]);
    }
}

// ---------------- launch ----------------
extern "C" void kernel_launch(void* const* d_in, const int* in_sizes, int n_in,
                              void* d_out, int out_size) {
    const float* x   = (const float*)d_in[0];
    const int*   ei  = (const int*)d_in[1];
    const float* W1  = (const float*)d_in[2];
    const float* as1 = (const float*)d_in[3];
    const float* ad1 = (const float*)d_in[4];
    const float* b1  = (const float*)d_in[5];
    const float* W2  = (const float*)d_in[6];
    const float* as2 = (const float*)d_in[7];
    const float* ad2 = (const float*)d_in[8];
    const float* b2  = (const float*)d_in[9];
    const float* W3  = (const float*)d_in[10];
    const float* as3 = (const float*)d_in[11];
    const float* ad3 = (const float*)d_in[12];
    const float* b3  = (const float*)d_in[13];
    float* out = (float*)d_out;

    __half2* h16;
    float*   hf;
    cudaGetSymbolAddress((void**)&h16, g_h16);
    cudaGetSymbolAddress((void**)&hf,  g_hf);

    // smem: As KS*132 + Bs F*64 + 128
    const size_t smem128 = (size_t)(32 * 132 + 128 * 64 + 128) * 4;  // 50176
    const size_t smem64  = (size_t)(32 * 132 + 64 * 64 + 128) * 4;   // 33792
    cudaFuncSetAttribute((const void*)k_gemm<128, 32>, cudaFuncAttributeMaxDynamicSharedMemorySize, (int)smem128);
    cudaFuncSetAttribute((const void*)k_gemm<64, 32>,  cudaFuncAttributeMaxDynamicSharedMemorySize, (int)smem64);

    const int gemm_grid = (N_NODES + 127) / 128;        // 391
    const int edge_grid = (N_NODES * 32 + 255) / 256;   // 6250

    // Fork a side stream (capture-legal via events) so the CSR build overlaps GEMM1.
    // CSR is enqueued FIRST (measured faster than gemm-first: its short kernels grab
    // SMs immediately and finish inside gemm1's shadow). Handles are leaked
    // intentionally (destroying mid-capture is hazardous; a few host objects per
    // kernel_launch call is harmless).
    cudaStream_t s2;
    cudaStreamCreateWithFlags(&s2, cudaStreamNonBlocking);
    cudaEvent_t evFork, evJoin;
    cudaEventCreateWithFlags(&evFork, cudaEventDisableTiming);
    cudaEventCreateWithFlags(&evJoin, cudaEventDisableTiming);

    cudaEventRecord(evFork, 0);
    cudaStreamWaitEvent(s2, evFork, 0);

    // CSR build on side stream (depends only on edge_index)
    k_hist<<<(E_EDGES / 4 + 255) / 256, 256, 0, s2>>>(ei);
    k_offsets<<<(N_NODES + 1023) / 1024, 1024, 0, s2>>>();
    k_fill<<<(E_EDGES / 4 + N_NODES + 255) / 256, 256, 0, s2>>>(ei);
    cudaEventRecord(evJoin, s2);

    // GEMM1 on main stream, concurrent with CSR build
    k_gemm<128, 32><<<gemm_grid, 256, smem128>>>(x, W1, HID, as1, ad1, h16);

    // join: edge1 needs both CSR and GEMM1
    cudaStreamWaitEvent(0, evJoin, 0);
    k_edge<HID, true><<<edge_grid, 256>>>(h16, b1, hf);
    // layer 2
    k_gemm<64, 32><<<gemm_grid, 256, smem64>>>(hf, W2, HID, as2, ad2, h16);
    k_edge<HID, true><<<edge_grid, 256>>>(h16, b2, hf);
    // layer 3 (O=40, padded to 64 internally)
    k_gemm<64, 32><<<gemm_grid, 256, smem64>>>(hf, W3, CLS, as3, ad3, h16);
    k_edge<CLS, false><<<edge_grid, 256>>>(h16, b3, out);
}